// round 4
// baseline (speedup 1.0000x reference)
#include <cuda_runtime.h>
#include <cuda_fp16.h>
#include <cstdint>

// DRR renderer: line integrals of trilinearly-interpolated 256^3 volume along
// point-source -> detector rays.
//
// R3: branchless inner loop. All samples in the slab-clipped range load from
// clamped (always-valid) coords with constant corner offsets; the outside mask
// is a multiply. No control flow in the body -> ptxas front-batches the 8
// LDGs across the unroll-4 window (MLP ~32) instead of serializing per sample.

#define DV 256
#define DV2 (DV * DV)

__device__ __half g_volT[DV * DV * DV];  // 32 MB, x-fastest layout

// -------- transpose: g_volT[k*DV2 + j*DV + i] = (half)vol[i*DV2 + j*DV + k] --------
__global__ void __launch_bounds__(256) transpose_vol(const float* __restrict__ v) {
    __shared__ float tile[32][65];            // [k_local][i_local(64)+pad]
    const int j  = blockIdx.z;
    const int i0 = blockIdx.y * 64;
    const int k0 = blockIdx.x * 32;
    const int tx = threadIdx.x, ty = threadIdx.y;

#pragma unroll
    for (int n = 0; n < 8; n++) {
        const int il = ty + n * 8;
        tile[tx][il] = v[(size_t)(i0 + il) * DV2 + j * DV + (k0 + tx)];
    }
    __syncthreads();
#pragma unroll
    for (int n = 0; n < 4; n++) {
        const int kl = ty + n * 8;
        const __half2 h = __floats2half2_rn(tile[kl][2 * tx], tile[kl][2 * tx + 1]);
        ((__half2*)g_volT)[(((size_t)(k0 + kl) * DV2 + j * DV + i0) >> 1) + tx] = h;
    }
}

// ----------------------------- main ray kernel ------------------------------
// 2 threads per ray: sub-thread handles samples s0+sub, s0+sub+2, ...
__global__ void __launch_bounds__(256) drr_kernel(
    const float* __restrict__ src,
    const float* __restrict__ tgt,
    const float* __restrict__ spacing,
    const float* __restrict__ origin,
    const int*   __restrict__ nptr,
    float* __restrict__ out,
    int n_rays)
{
    const int tid = blockIdx.x * blockDim.x + threadIdx.x;
    const int r   = tid >> 1;
    const int sub = tid & 1;
    if (r >= n_rays) return;

    const int n = nptr ? __ldg(nptr) : 128;

    const float ox = __ldg(origin + 0), oy = __ldg(origin + 1), oz = __ldg(origin + 2);
    const float hx = __ldg(spacing + 0), hy = __ldg(spacing + 1), hz = __ldg(spacing + 2);

    const float sxm = __ldg(src + 3 * r + 0);
    const float sym = __ldg(src + 3 * r + 1);
    const float szm = __ldg(src + 3 * r + 2);
    const float txm = __ldg(tgt + 3 * r + 0);
    const float tym = __ldg(tgt + 3 * r + 1);
    const float tzm = __ldg(tgt + 3 * r + 2);

    const float rx = txm - sxm, ry = tym - sym, rz = tzm - szm;
    const float raylen = sqrtf(fmaf(rx, rx, fmaf(ry, ry, rz * rz)));

    // voxel-space parametrization: idx(t) = p0 + t * d,  t = s/(n-1)
    const float p0x = (sxm - ox) / hx, p0y = (sym - oy) / hy, p0z = (szm - oz) / hz;
    const float dx = rx / hx, dy = ry / hy, dz = rz / hz;

    const float DM1 = (float)(DV - 1);

    // slab clip in t
    float tlo = 0.0f, thi = 1.0f;
    bool empty = false;
    {
        float p0[3] = {p0x, p0y, p0z};
        float dd[3] = {dx, dy, dz};
#pragma unroll
        for (int a = 0; a < 3; a++) {
            if (fabsf(dd[a]) > 1e-8f) {
                float inv = 1.0f / dd[a];
                float t1 = (0.0f - p0[a]) * inv;
                float t2 = (DM1 - p0[a]) * inv;
                tlo = fmaxf(tlo, fminf(t1, t2));
                thi = fminf(thi, fmaxf(t1, t2));
            } else if (p0[a] < 0.0f || p0[a] > DM1) {
                empty = true;
            }
        }
    }

    float acc = 0.0f;
    const float nm1 = (float)(n - 1);
    const float invn = (n > 1) ? 1.0f / nm1 : 0.0f;

    if (!empty && thi >= tlo) {
        const int s0 = max(0, (int)floorf(tlo * nm1));
        const int s1 = min(n - 1, (int)ceilf(thi * nm1));

#pragma unroll 4
        for (int s = s0 + sub; s <= s1; s += 2) {
            const float t  = (float)s * invn;
            const float ix = fmaf(t, dx, p0x);
            const float iy = fmaf(t, dy, p0y);
            const float iz = fmaf(t, dz, p0z);

            // outside mask (branchless)
            const bool inside = (ix >= 0.0f) & (ix <= DM1) &
                                (iy >= 0.0f) & (iy <= DM1) &
                                (iz >= 0.0f) & (iz <= DM1);
            const float m = inside ? 1.0f : 0.0f;

            // clamp to valid range; i0<=254 with wx=ix-i0 handles ix==255 exactly
            const float cx = fminf(fmaxf(ix, 0.0f), DM1);
            const float cy = fminf(fmaxf(iy, 0.0f), DM1);
            const float cz = fminf(fmaxf(iz, 0.0f), DM1);
            const int i0 = min((int)cx, DV - 2);
            const int j0 = min((int)cy, DV - 2);
            const int k0 = min((int)cz, DV - 2);
            const float wx = cx - (float)i0;
            const float wy = cy - (float)j0;
            const float wz = cz - (float)k0;

            const __half* b = g_volT + ((k0 * DV + j0) * DV + i0);

            const float v000 = __half2float(__ldg(b));
            const float v100 = __half2float(__ldg(b + 1));
            const float v010 = __half2float(__ldg(b + DV));
            const float v110 = __half2float(__ldg(b + DV + 1));
            const float v001 = __half2float(__ldg(b + DV2));
            const float v101 = __half2float(__ldg(b + DV2 + 1));
            const float v011 = __half2float(__ldg(b + DV2 + DV));
            const float v111 = __half2float(__ldg(b + DV2 + DV + 1));

            // 7-lerp trilinear: lerp(a,b,w) = fma(w, b-a, a)
            const float c00 = fmaf(wx, v100 - v000, v000);
            const float c01 = fmaf(wx, v110 - v010, v010);
            const float c10 = fmaf(wx, v101 - v001, v001);
            const float c11 = fmaf(wx, v111 - v011, v011);
            const float c0  = fmaf(wy, c01 - c00, c00);
            const float c1  = fmaf(wy, c11 - c10, c10);
            const float smp = fmaf(wz, c1 - c0, c0);
            acc = fmaf(m, smp, acc);
        }
    }

    // pair reduction across the 2 sub-threads of this ray
    acc += __shfl_xor_sync(0xFFFFFFFFu, acc, 1);

    if (sub == 0) out[r] = acc * raylen / (float)n;
}

extern "C" void kernel_launch(void* const* d_in, const int* in_sizes, int n_in,
                              void* d_out, int out_size) {
    const float* src     = (const float*)d_in[0];
    const float* tgt     = (const float*)d_in[1];
    const float* density = (const float*)d_in[2];
    const float* spacing = (const float*)d_in[3];
    const float* origin  = (const float*)d_in[4];
    const int*   nptr    = (n_in > 5) ? (const int*)d_in[5] : nullptr;
    float* out = (float*)d_out;

    // 1) transpose volume into x-fastest fp16 scratch
    dim3 tb(32, 8);
    dim3 tg(DV / 32, DV / 64, DV);
    transpose_vol<<<tg, tb>>>(density);

    // 2) two threads per ray
    const int threads = 256;
    const int total   = out_size * 2;
    const int blocks  = (total + threads - 1) / threads;
    drr_kernel<<<blocks, threads>>>(src, tgt, spacing, origin, nptr, out, out_size);
}

// round 6
// speedup vs baseline: 1.4571x; 1.4571x over previous
#include <cuda_runtime.h>
#include <cuda_fp16.h>
#include <cstdint>

// DRR renderer: line integrals of trilinearly-interpolated 256^3 volume.
//
// R5 (= R4 with compile fix): instruction-diet inner loop.
//  - volume transposed to x-fastest fp16 (32MB, L2-resident).
//  - per sample: ONE flat 32-bit offset; 8 aligned 32-bit loads (2 per row,
//    covering i0/i0+1 regardless of parity) with immediate offsets;
//    PRMT-select of the needed half pair; converts; 7-lerp trilinear.
//  - no inside-mask: sample range [ceil(tlo*nm1-eps), floor(thi*nm1+eps)]
//    is inside by construction; float clamp to [0,254.99998] guards memory.

#define DV 256
#define DV2 (DV * DV)

__device__ __half g_volT[DV * DV * DV];  // 32 MB, x-fastest layout

__device__ __forceinline__ __half2 u32_as_half2(uint32_t x) {
    __half2 h;
    *reinterpret_cast<uint32_t*>(&h) = x;
    return h;
}

// -------- transpose: g_volT[k*DV2 + j*DV + i] = (half)vol[i*DV2 + j*DV + k] --------
__global__ void __launch_bounds__(256) transpose_vol(const float* __restrict__ v) {
    __shared__ float tile[32][65];            // [k_local][i_local(64)+pad]
    const int j  = blockIdx.z;
    const int i0 = blockIdx.y * 64;
    const int k0 = blockIdx.x * 32;
    const int tx = threadIdx.x, ty = threadIdx.y;

#pragma unroll
    for (int n = 0; n < 8; n++) {
        const int il = ty + n * 8;
        tile[tx][il] = v[(size_t)(i0 + il) * DV2 + j * DV + (k0 + tx)];
    }
    __syncthreads();
#pragma unroll
    for (int n = 0; n < 4; n++) {
        const int kl = ty + n * 8;
        const __half2 h = __floats2half2_rn(tile[kl][2 * tx], tile[kl][2 * tx + 1]);
        ((__half2*)g_volT)[(((size_t)(k0 + kl) * DV2 + j * DV + i0) >> 1) + tx] = h;
    }
}

// ----------------------------- main ray kernel ------------------------------
// 2 threads per ray: sub-thread handles samples s0+sub, s0+sub+2, ...
__global__ void __launch_bounds__(256) drr_kernel(
    const float* __restrict__ src,
    const float* __restrict__ tgt,
    const float* __restrict__ spacing,
    const float* __restrict__ origin,
    const int*   __restrict__ nptr,
    float* __restrict__ out,
    int n_rays)
{
    const int tid = blockIdx.x * blockDim.x + threadIdx.x;
    const int r   = tid >> 1;
    const int sub = tid & 1;
    if (r >= n_rays) return;

    const int n = nptr ? __ldg(nptr) : 128;

    const float ox = __ldg(origin + 0), oy = __ldg(origin + 1), oz = __ldg(origin + 2);
    const float hx = __ldg(spacing + 0), hy = __ldg(spacing + 1), hz = __ldg(spacing + 2);

    const float sxm = __ldg(src + 3 * r + 0);
    const float sym = __ldg(src + 3 * r + 1);
    const float szm = __ldg(src + 3 * r + 2);
    const float txm = __ldg(tgt + 3 * r + 0);
    const float tym = __ldg(tgt + 3 * r + 1);
    const float tzm = __ldg(tgt + 3 * r + 2);

    const float rx = txm - sxm, ry = tym - sym, rz = tzm - szm;
    const float raylen = sqrtf(fmaf(rx, rx, fmaf(ry, ry, rz * rz)));

    // voxel-space parametrization: idx(t) = p0 + t * d,  t = s/(n-1)
    const float p0x = (sxm - ox) / hx, p0y = (sym - oy) / hy, p0z = (szm - oz) / hz;
    const float dx = rx / hx, dy = ry / hy, dz = rz / hz;

    const float DM1 = (float)(DV - 1);

    // slab clip in t
    float tlo = 0.0f, thi = 1.0f;
    bool empty = false;
    {
        float p0[3] = {p0x, p0y, p0z};
        float dd[3] = {dx, dy, dz};
#pragma unroll
        for (int a = 0; a < 3; a++) {
            if (fabsf(dd[a]) > 1e-8f) {
                float inv = 1.0f / dd[a];
                float t1 = (0.0f - p0[a]) * inv;
                float t2 = (DM1 - p0[a]) * inv;
                tlo = fmaxf(tlo, fminf(t1, t2));
                thi = fminf(thi, fmaxf(t1, t2));
            } else if (p0[a] < 0.0f || p0[a] > DM1) {
                empty = true;
            }
        }
    }

    float acc = 0.0f;
    const float nm1 = (float)(n - 1);
    const float invn = (n > 1) ? 1.0f / nm1 : 0.0f;

    if (!empty && thi >= tlo) {
        // samples strictly within [tlo,thi] -> inside by construction
        const int s0 = max(0, (int)ceilf(fmaf(tlo, nm1, -1e-3f)));
        const int s1 = min(n - 1, (int)floorf(fmaf(thi, nm1, 1e-3f)));

        const uint32_t* __restrict__ h2 = (const uint32_t*)g_volT;
        const float CMAX = 254.99998f;   // floor <= 254, stays in-bounds

#pragma unroll 4
        for (int s = s0 + sub; s <= s1; s += 2) {
            const float t  = (float)s * invn;
            const float ix = fmaf(t, dx, p0x);
            const float iy = fmaf(t, dy, p0y);
            const float iz = fmaf(t, dz, p0z);

            const float cx = fminf(fmaxf(ix, 0.0f), CMAX);
            const float cy = fminf(fmaxf(iy, 0.0f), CMAX);
            const float cz = fminf(fmaxf(iz, 0.0f), CMAX);
            const int i0 = (int)cx, j0 = (int)cy, k0 = (int)cz;
            const float wx = cx - (float)i0;
            const float wy = cy - (float)j0;
            const float wz = cz - (float)k0;

            // flat half2 element index of the aligned pair containing i0
            const int e = ((k0 << 16) + (j0 << 8) + i0) >> 1;
            const uint32_t sel = (i0 & 1) ? 0x5432u : 0x3210u;

            // rows: (j0,k0), (j0+1,k0), (j0,k0+1), (j0+1,k0+1)
            const uint32_t a0 = __ldg(h2 + e);
            const uint32_t b0 = __ldg(h2 + e + 1);
            const uint32_t a1 = __ldg(h2 + e + 128);
            const uint32_t b1 = __ldg(h2 + e + 129);
            const uint32_t a2 = __ldg(h2 + e + 32768);
            const uint32_t b2 = __ldg(h2 + e + 32769);
            const uint32_t a3 = __ldg(h2 + e + 32896);
            const uint32_t b3 = __ldg(h2 + e + 32897);

            const __half2 p0h = u32_as_half2(__byte_perm(a0, b0, sel));
            const __half2 p1h = u32_as_half2(__byte_perm(a1, b1, sel));
            const __half2 p2h = u32_as_half2(__byte_perm(a2, b2, sel));
            const __half2 p3h = u32_as_half2(__byte_perm(a3, b3, sel));

            const float v000 = __low2float(p0h), v100 = __high2float(p0h);
            const float v010 = __low2float(p1h), v110 = __high2float(p1h);
            const float v001 = __low2float(p2h), v101 = __high2float(p2h);
            const float v011 = __low2float(p3h), v111 = __high2float(p3h);

            // 7-lerp trilinear: lerp(a,b,w) = fma(w, b-a, a)
            const float c00 = fmaf(wx, v100 - v000, v000);
            const float c01 = fmaf(wx, v110 - v010, v010);
            const float c10 = fmaf(wx, v101 - v001, v001);
            const float c11 = fmaf(wx, v111 - v011, v011);
            const float c0  = fmaf(wy, c01 - c00, c00);
            const float c1  = fmaf(wy, c11 - c10, c10);
            acc += fmaf(wz, c1 - c0, c0);
        }
    }

    // pair reduction across the 2 sub-threads of this ray
    acc += __shfl_xor_sync(0xFFFFFFFFu, acc, 1);

    if (sub == 0) out[r] = acc * raylen / (float)n;
}

extern "C" void kernel_launch(void* const* d_in, const int* in_sizes, int n_in,
                              void* d_out, int out_size) {
    const float* src     = (const float*)d_in[0];
    const float* tgt     = (const float*)d_in[1];
    const float* density = (const float*)d_in[2];
    const float* spacing = (const float*)d_in[3];
    const float* origin  = (const float*)d_in[4];
    const int*   nptr    = (n_in > 5) ? (const int*)d_in[5] : nullptr;
    float* out = (float*)d_out;

    // 1) transpose volume into x-fastest fp16 scratch
    dim3 tb(32, 8);
    dim3 tg(DV / 32, DV / 64, DV);
    transpose_vol<<<tg, tb>>>(density);

    // 2) two threads per ray
    const int threads = 256;
    const int total   = out_size * 2;
    const int blocks  = (total + threads - 1) / threads;
    drr_kernel<<<blocks, threads>>>(src, tgt, spacing, origin, nptr, out, out_size);
}